// round 13
// baseline (speedup 1.0000x reference)
#include <cuda_runtime.h>

#define HIDDEN 51
#define JP 64
#define KH 26            // k-rows per half; 52 rows: 0..50 = U, row 51 = combined bias (h==1)
#define KROWS 52
#define ROWB 5           // ull per h row (4 batches + 1 pad) -> 40B stride, conflict-free B writes
#define L_SEQ 1000
#define NBLK 128
#define THREADS 256      // A-crew 128 + B-crew 128; two batch-sets of 4

typedef unsigned long long ull;

// Gate-interleaved weights: g_U4[row*JP + j] = (i,f,g,o); row 51 = combined bias
__device__ float4 g_U4[KROWS * JP];
__device__ float4 g_W4[JP];   // x weights per j
__device__ float  g_L[JP];    // lin_w per j

// ---------- f32x2 helpers (exact packed fp32) ----------
__device__ __forceinline__ ull pk2(float lo, float hi) {
    ull r; asm("mov.b64 %0, {%1, %2};" : "=l"(r) : "f"(lo), "f"(hi)); return r;
}
__device__ __forceinline__ void up2(float& lo, float& hi, ull v) {
    asm("mov.b64 {%0, %1}, %2;" : "=f"(lo), "=f"(hi) : "l"(v));
}
__device__ __forceinline__ ull f2fma(ull a, ull b, ull c) {
    ull d; asm("fma.rn.f32x2 %0, %1, %2, %3;" : "=l"(d) : "l"(a), "l"(b), "l"(c)); return d;
}
__device__ __forceinline__ ull f2add(ull a, ull b) {
    ull d; asm("add.rn.f32x2 %0, %1, %2;" : "=l"(d) : "l"(a), "l"(b)); return d;
}
// accurate fast tanh: 1 - 2/(exp(2x)+1); saturates correctly at +-inf
__device__ __forceinline__ float fast_tanh(float xv) {
    float e;
    asm("ex2.approx.f32 %0, %1;" : "=f"(e) : "f"(xv * 2.8853900817779268f));
    float r;
    asm("rcp.approx.f32 %0, %1;" : "=f"(r) : "f"(e + 1.0f));
    return fmaf(-2.0f, r, 1.0f);
}

// ---------- prep ----------
__global__ void prep_kernel(const float* __restrict__ W_w, const float* __restrict__ W_b,
                            const float* __restrict__ U_w, const float* __restrict__ U_b,
                            const float* __restrict__ lin_w) {
    int i = blockIdx.x * 128 + threadIdx.x;   // 0 .. 3327 (52 rows x 64 j)
    if (i >= KROWS * JP) return;
    int k = i >> 6, j = i & 63;
    float4 u = make_float4(0.f, 0.f, 0.f, 0.f);
    if (j < HIDDEN) {
        if (k < HIDDEN) {
            u.x = U_w[(0 * HIDDEN + j) * HIDDEN + k];
            u.y = U_w[(1 * HIDDEN + j) * HIDDEN + k];
            u.z = U_w[(2 * HIDDEN + j) * HIDDEN + k];
            u.w = U_w[(3 * HIDDEN + j) * HIDDEN + k];
        } else {                              // row 51 = combined bias (h == 1)
            u.x = W_b[0 * HIDDEN + j] + U_b[0 * HIDDEN + j];
            u.y = W_b[1 * HIDDEN + j] + U_b[1 * HIDDEN + j];
            u.z = W_b[2 * HIDDEN + j] + U_b[2 * HIDDEN + j];
            u.w = W_b[3 * HIDDEN + j] + U_b[3 * HIDDEN + j];
        }
    }
    g_U4[i] = u;
    if (i < JP) {
        float4 w = make_float4(0.f, 0.f, 0.f, 0.f);
        float lw = 0.f;
        if (i < HIDDEN) {
            w.x = W_w[0 * HIDDEN + i]; w.y = W_w[1 * HIDDEN + i];
            w.z = W_w[2 * HIDDEN + i]; w.w = W_w[3 * HIDDEN + i];
            lw = lin_w[i];
        }
        g_W4[i] = w; g_L[i] = lw;
    }
}

// ---------- main: warp-specialized A/B pipeline over two batch-sets ----------
// A-crew: tid 0..127   = (half, ja): partial gates for the slot's A-set.
// B-crew: tid 128..255 = (jb, bp):  combine/update for the slot's B-set.
// Slot s: A(set s&1, t=s>>1) || B(set !(s&1), t=(s-1)>>1); ONE __syncthreads per slot.

// A part: partial gates for set SA from h_shd[SA] -> psum[SA]
#define APART(SA)                                                               \
    {                                                                           \
        ull ai0=0,ag0=0, ai1=0,ag1=0, ai2=0,ag2=0, ai3=0,ag3=0;                 \
        const ull* hr = &h_shd[SA][half * KH][0];                               \
        _Pragma("unroll")                                                       \
        for (int kk = 0; kk < KH; kk++) {                                       \
            ulonglong2 h01 = *(const ulonglong2*)&hr[kk * ROWB + 0];            \
            ulonglong2 h23 = *(const ulonglong2*)&hr[kk * ROWB + 2];            \
            ai0 = f2fma(h01.x, u_if[kk], ai0); ag0 = f2fma(h01.x, u_go[kk], ag0);\
            ai1 = f2fma(h01.y, u_if[kk], ai1); ag1 = f2fma(h01.y, u_go[kk], ag1);\
            ai2 = f2fma(h23.x, u_if[kk], ai2); ag2 = f2fma(h23.x, u_go[kk], ag2);\
            ai3 = f2fma(h23.y, u_if[kk], ai3); ag3 = f2fma(h23.y, u_go[kk], ag3);\
        }                                                                       \
        { ulonglong2 v; v.x=ai0; v.y=ag0; psum[SA][half][0][ja] = v; }          \
        { ulonglong2 v; v.x=ai1; v.y=ag1; psum[SA][half][1][ja] = v; }          \
        { ulonglong2 v; v.x=ai2; v.y=ag2; psum[SA][half][2][ja] = v; }          \
        { ulonglong2 v; v.x=ai3; v.y=ag3; psum[SA][half][3][ja] = v; }          \
    }

// B part: combine psum[SB] at time TB, update c/h, lagged out store, redp write
#define BPART(SB, TB)                                                           \
    {                                                                           \
        const int tB_ = (TB);                                                   \
        if (tB_ >= 1 && bt < 4) {                                               \
            int b = bt, pb = (tB_ - 1) & 1;                                     \
            float acc = lbv;                                                    \
            _Pragma("unroll")                                                   \
            for (int w = 0; w < 4; w++) {                                       \
                float lo, hi; up2(lo, hi, redp[SB][pb][w][b >> 1]);             \
                acc += (b & 1) ? hi : lo;                                       \
            }                                                                   \
            out[(b0 + (SB) * 4 + b) * L_SEQ + (tB_ - 1)] = acc;                 \
        }                                                                       \
        float prod0, prod1;                                                     \
        {   int b = bp * 2;                                                     \
            ulonglong2 p0 = psum[SB][0][b][jb], p1 = psum[SB][1][b][jb];        \
            ull sif = f2add(p0.x, p1.x), sgo = f2add(p0.y, p1.y);               \
            float gi, gf, gg, go; up2(gi, gf, sif); up2(gg, go, sgo);           \
            gi = fmaf(xq[SB][0], wv.x, gi); gf = fmaf(xq[SB][0], wv.y, gf);     \
            gg = fmaf(xq[SB][0], wv.z, gg); go = fmaf(xq[SB][0], wv.w, go);     \
            c[SB][0] = fmaf(gf, c[SB][0], gi * gg);  /* faithful: no sigmoids */\
            float h = go * fast_tanh(c[SB][0]);                                 \
            if (jb < HIDDEN) h_shd[SB][jb][b] = pk2(h, h);                      \
            prod0 = h * lw;                                                     \
        }                                                                       \
        {   int b = bp * 2 + 1;                                                 \
            ulonglong2 p0 = psum[SB][0][b][jb], p1 = psum[SB][1][b][jb];        \
            ull sif = f2add(p0.x, p1.x), sgo = f2add(p0.y, p1.y);               \
            float gi, gf, gg, go; up2(gi, gf, sif); up2(gg, go, sgo);           \
            gi = fmaf(xq[SB][1], wv.x, gi); gf = fmaf(xq[SB][1], wv.y, gf);     \
            gg = fmaf(xq[SB][1], wv.z, gg); go = fmaf(xq[SB][1], wv.w, go);     \
            c[SB][1] = fmaf(gf, c[SB][1], gi * gg);                             \
            float h = go * fast_tanh(c[SB][1]);                                 \
            if (jb < HIDDEN) h_shd[SB][jb][b] = pk2(h, h);                      \
            prod1 = h * lw;                                                     \
        }                                                                       \
        int tn = (tB_ + 1 < L_SEQ) ? tB_ + 1 : tB_;                             \
        xq[SB][0] = x[(b0 + (SB) * 4 + bp * 2 + 0) * L_SEQ + tn];               \
        xq[SB][1] = x[(b0 + (SB) * 4 + bp * 2 + 1) * L_SEQ + tn];               \
        prod0 += __shfl_xor_sync(0xffffffffu, prod0, 2);                        \
        prod1 += __shfl_xor_sync(0xffffffffu, prod1, 2);                        \
        prod0 += __shfl_xor_sync(0xffffffffu, prod0, 4);                        \
        prod1 += __shfl_xor_sync(0xffffffffu, prod1, 4);                        \
        prod0 += __shfl_xor_sync(0xffffffffu, prod0, 8);                        \
        prod1 += __shfl_xor_sync(0xffffffffu, prod1, 8);                        \
        prod0 += __shfl_xor_sync(0xffffffffu, prod0, 16);                       \
        prod1 += __shfl_xor_sync(0xffffffffu, prod1, 16);                       \
        if (lane < 2) redp[SB][tB_ & 1][bw][lane] = pk2(prod0, prod1);          \
    }

__global__ void __launch_bounds__(THREADS, 1)
lstm_main(const float* __restrict__ x, const float* __restrict__ lin_b,
          float* __restrict__ out) {
    __shared__ __align__(16) ull        h_shd[2][KROWS][ROWB];   // [set][row][(h,h) x4 + pad]
    __shared__ __align__(16) ulonglong2 psum[2][2][4][JP];       // [set][half][batch][j]
    __shared__ ull redp[2][2][4][2];                             // [set][t&1][B-warp][bp]

    const int tid  = threadIdx.x;
    const bool isA = tid < 128;
    const int half = (tid >> 6) & 1;   // A-crew k-half
    const int ja   = tid & 63;         // A-crew hidden unit
    const int bt   = tid & 127;        // B-crew local id
    const int jb   = bt >> 1;          // B-crew hidden unit
    const int bp   = bt & 1;           // B-crew batch-pair (batches bp*2, bp*2+1)
    const int lane = tid & 31;
    const int bw   = bt >> 5;          // B-warp index 0..3
    const int b0   = blockIdx.x * 8;

    // A-crew: register U (gate-packed pairs), bias folded at row 51
    ull u_if[KH], u_go[KH];
    if (isA) {
#pragma unroll
        for (int kk = 0; kk < KH; kk++) {
            float4 u = g_U4[(half * KH + kk) * JP + ja];
            u_if[kk] = pk2(u.x, u.y);
            u_go[kk] = pk2(u.z, u.w);
        }
    }
    // B-crew state
    float4 wv = make_float4(0.f, 0.f, 0.f, 0.f);
    float lw = 0.f;
    const float lbv = lin_b[0];
    float c[2][2]  = {{0.f, 0.f}, {0.f, 0.f}};   // [set][s] — constant-indexed only
    float xq[2][2] = {{0.f, 0.f}, {0.f, 0.f}};
    if (!isA) {
        wv = g_W4[jb]; lw = g_L[jb];
        xq[0][0] = x[(b0 + bp * 2 + 0) * L_SEQ];
        xq[0][1] = x[(b0 + bp * 2 + 1) * L_SEQ];
        xq[1][0] = x[(b0 + 4 + bp * 2 + 0) * L_SEQ];
        xq[1][1] = x[(b0 + 4 + bp * 2 + 1) * L_SEQ];
    }

    // init h: zeros; bias row 51 = (1,1) in batch cols, both sets
    for (int i = tid; i < 2 * KROWS * ROWB; i += THREADS) {
        int row = (i / ROWB) % KROWS;
        int col = i % ROWB;
        ((ull*)h_shd)[i] = (row == HIDDEN && col < 4) ? pk2(1.f, 1.f) : 0ULL;
    }
    __syncthreads();

    for (int m = 0; m < L_SEQ; ++m) {
        // slot 2m: A(S0, m) || B(S1, m-1)
        if (isA) { APART(0) } else if (m > 0) { BPART(1, m - 1) }
        __syncthreads();
        // slot 2m+1: A(S1, m) || B(S0, m)
        if (isA) { APART(1) } else { BPART(0, m) }
        __syncthreads();
    }
    // final slot 2L: B(S1, L-1) only
    if (!isA) { BPART(1, L_SEQ - 1) }
    __syncthreads();

    // flush out for t = L-1, both sets (B-crew threads; lbv/redp available)
    if (!isA && bt < 8) {
        int set = bt >> 2, b = bt & 3, pb = (L_SEQ - 1) & 1;
        float acc = lbv;
#pragma unroll
        for (int w = 0; w < 4; w++) {
            float lo, hi; up2(lo, hi, redp[set][pb][w][b >> 1]);
            acc += (b & 1) ? hi : lo;
        }
        out[(b0 + set * 4 + b) * L_SEQ + (L_SEQ - 1)] = acc;
    }
}

extern "C" void kernel_launch(void* const* d_in, const int* in_sizes, int n_in,
                              void* d_out, int out_size) {
    (void)in_sizes; (void)n_in; (void)out_size;
    const float* x     = (const float*)d_in[0];
    const float* W_w   = (const float*)d_in[1];
    const float* W_b   = (const float*)d_in[2];
    const float* U_w   = (const float*)d_in[3];
    const float* U_b   = (const float*)d_in[4];
    const float* lin_w = (const float*)d_in[5];
    const float* lin_b = (const float*)d_in[6];
    // d_in[7] = future (static 0) — ignored.

    prep_kernel<<<26, 128>>>(W_w, W_b, U_w, U_b, lin_w);
    lstm_main<<<NBLK, THREADS>>>(x, lin_b, (float*)d_out);
}